// round 7
// baseline (speedup 1.0000x reference)
#include <cuda_runtime.h>
#include <cstdint>

// Shapes for PairwiseEmbeddings: B=2, L=256, H=256, A=32, P=64
#define LL   256
#define NB   2
#define NBI  512          // B*L
#define AA   32
#define PP   64
#define HH   256
#define CP   2048         // A*P : cp = c*64 + p  (c-major, p fastest)

// Scratch (no cudaMalloc allowed): ~4.4 MB total
__device__ float g_h [NBI * AA];        // h[bi][a]                64 KB
__device__ float g_hT[NB * AA * LL];    // hT[b][c][j]             64 KB
__device__ float g_wT[HH * AA];         // in_w transposed [k][a]  32 KB
__device__ float g_W2[AA * CP];         // W2[a][c*64+p]          256 KB
__device__ float g_M [NBI * CP];        // M[bi][c*64+p]            4 MB

// ---------------------------------------------------------------------------
// Prep: transpose out_w -> W2[a][c*64+p], transpose in_w -> wT[k][a]
// ---------------------------------------------------------------------------
__global__ void k_prep(const float* __restrict__ out_w,
                       const float* __restrict__ in_w) {
    int idx = blockIdx.x * 256 + threadIdx.x;       // grid covers 65536
    if (idx < PP * AA * AA) {
        int p = idx >> 10;          // out_w flat = p*1024 + a*32 + c
        int a = (idx >> 5) & 31;
        int c = idx & 31;
        g_W2[a * CP + c * PP + p] = out_w[idx];
    }
    if (idx < AA * HH) {
        int a = idx >> 8;           // in_w flat = a*256 + k
        int k = idx & 255;
        g_wT[k * AA + a] = in_w[idx];
    }
}

// ---------------------------------------------------------------------------
// K1: h[bi][a] = sum_k x[bi][k] * in_w[a][k] + in_b[a]
// One block per bi row. Tail also writes the [b][c][j] transpose for k_main.
// ---------------------------------------------------------------------------
__global__ void k_h(const float* __restrict__ x,
                    const float* __restrict__ in_b) {
    __shared__ float red[256];
    int t  = threadIdx.x;
    int bi = blockIdx.x;
    int a  = t & 31;
    int kc = t >> 5;                 // 0..7
    const float* xr = x + bi * HH + kc * 32;     // uniform per warp
    const float* wr = g_wT + (kc * 32) * AA + a; // coalesced over lanes
    float acc = 0.f;
#pragma unroll
    for (int k = 0; k < 32; k++)
        acc += xr[k] * wr[k * AA];
    red[t] = acc;
    __syncthreads();
    if (t < 32) {
        float s = in_b[t];
#pragma unroll
        for (int q = 0; q < 8; q++) s += red[q * 32 + t];
        g_h[bi * AA + t] = s;
        int b = bi >> 8, i = bi & 255;
        g_hT[b * (AA * LL) + t * LL + i] = s;    // transposed copy
    }
}

// ---------------------------------------------------------------------------
// K2: M[bi][cp] = sum_a h[bi][a] * W2[a][cp]
// ---------------------------------------------------------------------------
__global__ void k_m() {
    __shared__ float hs[16 * AA];    // 2 KB
    int t   = threadIdx.x;
    int bi0 = blockIdx.x * 16;
    int cp  = blockIdx.y * 256 + t;

    for (int idx = t; idx < 16 * AA; idx += 256)
        hs[idx] = g_h[bi0 * AA + idx];
    __syncthreads();

    float acc[16];
#pragma unroll
    for (int i = 0; i < 16; i++) acc[i] = 0.f;

#pragma unroll
    for (int a = 0; a < AA; a++) {
        float w = g_W2[a * CP + cp];
#pragma unroll
        for (int i = 0; i < 16; i++)
            acc[i] = fmaf(hs[i * AA + a], w, acc[i]);
    }
#pragma unroll
    for (int i = 0; i < 16; i++)
        g_M[(bi0 + i) * CP + cp] = acc[i];
}

// ---------------------------------------------------------------------------
// K3 (dominant): out[bi][j][p] = sum_c M[bi][c][p] * h[b][j][c] + table[d][p]
// One block per bi. Thread computes an 8j x 8p register tile:
//   pg = t & 7  -> p in [pg*8, pg*8+8)
//   jg = t >> 3 -> j in [jg*8, jg*8+8)
// Operands for iteration c+1 are prefetched into registers while iteration c
// computes (explicit SW pipeline, fully unrolled; the c<31 guard is
// compile-time under full unroll) — hides the 29-cyc LDS latency that left
// R4 at issue=24.6% / fma=23.9%.
// ---------------------------------------------------------------------------
__global__ void __launch_bounds__(256, 2)
k_main(const float* __restrict__ pos_w,
       const float* __restrict__ pos_b,
       const float* __restrict__ out_b,
       float* __restrict__ out) {
    __shared__ __align__(16) float ms [AA * PP];   // M[c][p]      8 KB
    __shared__ __align__(16) float hts[AA * LL];   // hT[c][j]    32 KB
    __shared__ __align__(16) float ps [17 * 68];   // pos table  4.6 KB

    int t  = threadIdx.x;
    int bi = blockIdx.x;
    int b  = bi >> 8;
    int i  = bi & 255;

    // M slice for this (b,i): contiguous, coalesced
    for (int idx = t; idx < AA * PP; idx += 256)
        ms[idx] = g_M[bi * CP + idx];

    // hT tile: already c-major in gmem -> coalesced read, conflict-free write
    const float* hb = &g_hT[b * (AA * LL)];
#pragma unroll
    for (int k = 0; k < 32; k++)
        hts[k * 256 + t] = hb[k * 256 + t];

    // fold out_b + pos_b into pos table: ps[d][p]
    for (int idx = t; idx < 17 * 64; idx += 256) {
        int d = idx >> 6, p = idx & 63;
        ps[d * 68 + p] = pos_w[p * 17 + d] + pos_b[p] + out_b[p];
    }
    __syncthreads();

    int pg = t & 7;        // p-group (8 p)
    int jg = t >> 3;       // j-group (8 j)

    unsigned long long acc[32];    // [jj][k] : jj*4 + k, k over 4 p-pairs
#pragma unroll
    for (int k = 0; k < 32; k++) acc[k] = 0ULL;

    const ulonglong2* msv = reinterpret_cast<const ulonglong2*>(ms);
    const float4*     hv  = reinterpret_cast<const float4*>(hts);

    // --- software-pipelined main loop (prefetch distance = 1 iteration) ---
    ulonglong2 ma = msv[pg * 2];
    ulonglong2 mb = msv[pg * 2 + 1];
    float4     h0 = hv[jg * 2];
    float4     h1 = hv[jg * 2 + 1];

#pragma unroll
    for (int c = 0; c < 32; c++) {
        ulonglong2 nma, nmb;
        float4     nh0, nh1;
        if (c < 31) {
            nma = msv[(c + 1) * 16 + pg * 2];
            nmb = msv[(c + 1) * 16 + pg * 2 + 1];
            nh0 = hv[(c + 1) * 64 + jg * 2];
            nh1 = hv[(c + 1) * 64 + jg * 2 + 1];
        }

        // splat all 8 h values up front (alu pipe, dual-issues vs FFMA2)
        unsigned long long h2[8];
        {
            float hvals[8] = {h0.x, h0.y, h0.z, h0.w, h1.x, h1.y, h1.z, h1.w};
#pragma unroll
            for (int jj = 0; jj < 8; jj++) {
                unsigned int hu = __float_as_uint(hvals[jj]);
                asm("mov.b64 %0, {%1, %1};" : "=l"(h2[jj]) : "r"(hu));
            }
        }
#pragma unroll
        for (int jj = 0; jj < 8; jj++) {
            asm("fma.rn.f32x2 %0, %1, %2, %0;" : "+l"(acc[jj*4+0]) : "l"(ma.x), "l"(h2[jj]));
            asm("fma.rn.f32x2 %0, %1, %2, %0;" : "+l"(acc[jj*4+1]) : "l"(ma.y), "l"(h2[jj]));
            asm("fma.rn.f32x2 %0, %1, %2, %0;" : "+l"(acc[jj*4+2]) : "l"(mb.x), "l"(h2[jj]));
            asm("fma.rn.f32x2 %0, %1, %2, %0;" : "+l"(acc[jj*4+3]) : "l"(mb.y), "l"(h2[jj]));
        }

        if (c < 31) { ma = nma; mb = nmb; h0 = nh0; h1 = nh1; }
    }

    // epilogue: packed add of rel-pos row, vectorized store
#pragma unroll
    for (int jj = 0; jj < 8; jj++) {
        int j = jg * 8 + jj;
        int d = i - j;
        d = (d < -8) ? -8 : ((d > 8) ? 8 : d);
        d += 8;
        const ulonglong2* pr =
            reinterpret_cast<const ulonglong2*>(&ps[d * 68 + pg * 8]);
        ulonglong2 p0 = pr[0], p1 = pr[1];
        ulonglong2 r0, r1;
        asm("add.rn.f32x2 %0, %1, %2;" : "=l"(r0.x) : "l"(acc[jj*4+0]), "l"(p0.x));
        asm("add.rn.f32x2 %0, %1, %2;" : "=l"(r0.y) : "l"(acc[jj*4+1]), "l"(p0.y));
        asm("add.rn.f32x2 %0, %1, %2;" : "=l"(r1.x) : "l"(acc[jj*4+2]), "l"(p1.x));
        asm("add.rn.f32x2 %0, %1, %2;" : "=l"(r1.y) : "l"(acc[jj*4+3]), "l"(p1.y));
        ulonglong2* ob = reinterpret_cast<ulonglong2*>(
            out + ((size_t)bi * LL + j) * PP + pg * 8);
        ob[0] = r0;
        ob[1] = r1;
    }
}

// ---------------------------------------------------------------------------
// Launch
// inputs (metadata order): inputs_embeds, in_w, in_b, out_w, out_b, pos_w, pos_b
// ---------------------------------------------------------------------------
extern "C" void kernel_launch(void* const* d_in, const int* in_sizes, int n_in,
                              void* d_out, int out_size) {
    const float* x     = (const float*)d_in[0];
    const float* in_w  = (const float*)d_in[1];
    const float* in_b  = (const float*)d_in[2];
    const float* out_w = (const float*)d_in[3];
    const float* out_b = (const float*)d_in[4];
    const float* pos_w = (const float*)d_in[5];
    const float* pos_b = (const float*)d_in[6];
    float* out = (float*)d_out;

    k_prep<<<256, 256>>>(out_w, in_w);
    k_h   <<<NBI, 256>>>(x, in_b);
    k_m   <<<dim3(32, 8), 256>>>();
    k_main<<<NBI, 256>>>(pos_w, pos_b, out_b, out);
}

// round 8
// speedup vs baseline: 1.0058x; 1.0058x over previous
#include <cuda_runtime.h>
#include <cstdint>

// Shapes for PairwiseEmbeddings: B=2, L=256, H=256, A=32, P=64
#define LL   256
#define NB   2
#define NBI  512          // B*L
#define AA   32
#define PP   64
#define HH   256
#define CP   2048         // A*P : cp = c*64 + p  (c-major, p fastest)

// Scratch (no cudaMalloc allowed): ~4.4 MB total
__device__ float g_h [NBI * AA];        // h[bi][a]                64 KB
__device__ float g_hT[NB * AA * LL];    // hT[b][c][j]             64 KB
__device__ float g_wT[HH * AA];         // in_w transposed [k][a]  32 KB
__device__ float g_W2[AA * CP];         // W2[a][c*64+p]          256 KB
__device__ float g_M [NBI * CP];        // M[bi][c*64+p]            4 MB

// ---------------------------------------------------------------------------
// Prep: transpose out_w -> W2[a][c*64+p], transpose in_w -> wT[k][a]
// ---------------------------------------------------------------------------
__global__ void k_prep(const float* __restrict__ out_w,
                       const float* __restrict__ in_w) {
    int idx = blockIdx.x * 256 + threadIdx.x;       // grid covers 65536
    if (idx < PP * AA * AA) {
        int p = idx >> 10;          // out_w flat = p*1024 + a*32 + c
        int a = (idx >> 5) & 31;
        int c = idx & 31;
        g_W2[a * CP + c * PP + p] = out_w[idx];
    }
    if (idx < AA * HH) {
        int a = idx >> 8;           // in_w flat = a*256 + k
        int k = idx & 255;
        g_wT[k * AA + a] = in_w[idx];
    }
}

// ---------------------------------------------------------------------------
// K1: h[bi][a] = sum_k x[bi][k] * in_w[a][k] + in_b[a]
// One block per bi row. Tail also writes the [b][c][j] transpose for k_main.
// ---------------------------------------------------------------------------
__global__ void k_h(const float* __restrict__ x,
                    const float* __restrict__ in_b) {
    __shared__ float red[256];
    int t  = threadIdx.x;
    int bi = blockIdx.x;
    int a  = t & 31;
    int kc = t >> 5;                 // 0..7
    const float* xr = x + bi * HH + kc * 32;     // uniform per warp
    const float* wr = g_wT + (kc * 32) * AA + a; // coalesced over lanes
    float acc = 0.f;
#pragma unroll
    for (int k = 0; k < 32; k++)
        acc += xr[k] * wr[k * AA];
    red[t] = acc;
    __syncthreads();
    if (t < 32) {
        float s = in_b[t];
#pragma unroll
        for (int q = 0; q < 8; q++) s += red[q * 32 + t];
        g_h[bi * AA + t] = s;
        int b = bi >> 8, i = bi & 255;
        g_hT[b * (AA * LL) + t * LL + i] = s;    // transposed copy
    }
}

// ---------------------------------------------------------------------------
// K2: M[bi][cp] = sum_a h[bi][a] * W2[a][cp]
// ---------------------------------------------------------------------------
__global__ void k_m() {
    __shared__ float hs[16 * AA];    // 2 KB
    int t   = threadIdx.x;
    int bi0 = blockIdx.x * 16;
    int cp  = blockIdx.y * 256 + t;

    for (int idx = t; idx < 16 * AA; idx += 256)
        hs[idx] = g_h[bi0 * AA + idx];
    __syncthreads();

    float acc[16];
#pragma unroll
    for (int i = 0; i < 16; i++) acc[i] = 0.f;

#pragma unroll
    for (int a = 0; a < AA; a++) {
        float w = g_W2[a * CP + cp];
#pragma unroll
        for (int i = 0; i < 16; i++)
            acc[i] = fmaf(hs[i * AA + a], w, acc[i]);
    }
#pragma unroll
    for (int i = 0; i < 16; i++)
        g_M[(bi0 + i) * CP + cp] = acc[i];
}

// ---------------------------------------------------------------------------
// K3 (dominant): out[bi][j][p] = sum_c M[bi][c][p] * h[b][j][c] + table[d][p]
// R8: occupancy-first redesign. Grid = 1024 CTAs (bi x j-half), thread tile
// 4j x 8p (16 packed accumulators, <=64 regs, 4 CTAs/SM = 8 warps/SMSP).
//   pg = t & 7  -> p = pg*8 .. pg*8+7
//   jg = t >> 3 -> j = j0 + jg*4 + jj, jj in 0..3
// Per c: 2 LDS.128 (M pairs) + 1 LDS.128 (h quad) + 4 splats + 16 FFMA2.
// ---------------------------------------------------------------------------
__global__ void __launch_bounds__(256, 4)
k_main(const float* __restrict__ pos_w,
       const float* __restrict__ pos_b,
       const float* __restrict__ out_b,
       float* __restrict__ out) {
    __shared__ __align__(16) float ms [AA * PP];    // M[c][p]       8 KB
    __shared__ __align__(16) float hts[AA * 128];   // hT[c][jl]    16 KB
    __shared__ __align__(16) float ps [17 * 68];    // pos table   4.6 KB

    int t   = threadIdx.x;
    int bi  = blockIdx.x >> 1;
    int jh  = blockIdx.x & 1;
    int j0  = jh * 128;
    int b   = bi >> 8;
    int i   = bi & 255;

    // M slice for this (b,i): contiguous, coalesced (2 float4 per thread)
    {
        const float4* src = reinterpret_cast<const float4*>(&g_M[bi * CP]);
        float4* dst = reinterpret_cast<float4*>(ms);
#pragma unroll
        for (int k = 0; k < 2; k++)
            dst[k * 256 + t] = src[k * 256 + t];
    }

    // hT tile: c-major rows, j-slice [j0, j0+128) (4 float4 per thread)
    {
        const float* hb = &g_hT[b * (AA * LL)];
#pragma unroll
        for (int k = 0; k < 4; k++) {
            int idx4 = k * 256 + t;            // 0..1023
            int c  = idx4 >> 5;
            int jl4 = idx4 & 31;
            reinterpret_cast<float4*>(hts)[c * 32 + jl4] =
                reinterpret_cast<const float4*>(hb + c * LL + j0)[jl4];
        }
    }

    // fold out_b + pos_b into pos table: ps[d][p]
    for (int idx = t; idx < 17 * 64; idx += 256) {
        int d = idx >> 6, p = idx & 63;
        ps[d * 68 + p] = pos_w[p * 17 + d] + pos_b[p] + out_b[p];
    }
    __syncthreads();

    int pg = t & 7;        // p-group (8 p)
    int jg = t >> 3;       // j-group (4 j), 0..31

    unsigned long long acc[16];    // [jj][k] : jj*4 + k, k over 4 p-pairs
#pragma unroll
    for (int k = 0; k < 16; k++) acc[k] = 0ULL;

    const ulonglong2* msv = reinterpret_cast<const ulonglong2*>(ms);
    const float4*     hv  = reinterpret_cast<const float4*>(hts);

#pragma unroll
    for (int c = 0; c < 32; c++) {
        // M[c][pg*8 .. pg*8+7]: float base c*64+pg*8 -> ull2 idx c*16+pg*2
        ulonglong2 ma = msv[c * 16 + pg * 2];
        ulonglong2 mb = msv[c * 16 + pg * 2 + 1];
        // h[c][jg*4 .. jg*4+3]: float base c*128+jg*4 -> float4 idx c*32+jg
        float4 h4 = hv[c * 32 + jg];

        float hvals[4] = {h4.x, h4.y, h4.z, h4.w};
#pragma unroll
        for (int jj = 0; jj < 4; jj++) {
            unsigned int hu = __float_as_uint(hvals[jj]);
            unsigned long long h2;
            asm("mov.b64 %0, {%1, %1};" : "=l"(h2) : "r"(hu));
            asm("fma.rn.f32x2 %0, %1, %2, %0;" : "+l"(acc[jj*4+0]) : "l"(ma.x), "l"(h2));
            asm("fma.rn.f32x2 %0, %1, %2, %0;" : "+l"(acc[jj*4+1]) : "l"(ma.y), "l"(h2));
            asm("fma.rn.f32x2 %0, %1, %2, %0;" : "+l"(acc[jj*4+2]) : "l"(mb.x), "l"(h2));
            asm("fma.rn.f32x2 %0, %1, %2, %0;" : "+l"(acc[jj*4+3]) : "l"(mb.y), "l"(h2));
        }
    }

    // epilogue: packed add of rel-pos row, vectorized store
#pragma unroll
    for (int jj = 0; jj < 4; jj++) {
        int j = j0 + jg * 4 + jj;
        int d = i - j;
        d = (d < -8) ? -8 : ((d > 8) ? 8 : d);
        d += 8;
        const ulonglong2* pr =
            reinterpret_cast<const ulonglong2*>(&ps[d * 68 + pg * 8]);
        ulonglong2 p0 = pr[0], p1 = pr[1];
        ulonglong2 r0, r1;
        asm("add.rn.f32x2 %0, %1, %2;" : "=l"(r0.x) : "l"(acc[jj*4+0]), "l"(p0.x));
        asm("add.rn.f32x2 %0, %1, %2;" : "=l"(r0.y) : "l"(acc[jj*4+1]), "l"(p0.y));
        asm("add.rn.f32x2 %0, %1, %2;" : "=l"(r1.x) : "l"(acc[jj*4+2]), "l"(p1.x));
        asm("add.rn.f32x2 %0, %1, %2;" : "=l"(r1.y) : "l"(acc[jj*4+3]), "l"(p1.y));
        ulonglong2* ob = reinterpret_cast<ulonglong2*>(
            out + ((size_t)bi * LL + j) * PP + pg * 8);
        ob[0] = r0;
        ob[1] = r1;
    }
}

// ---------------------------------------------------------------------------
// Launch
// inputs (metadata order): inputs_embeds, in_w, in_b, out_w, out_b, pos_w, pos_b
// ---------------------------------------------------------------------------
extern "C" void kernel_launch(void* const* d_in, const int* in_sizes, int n_in,
                              void* d_out, int out_size) {
    const float* x     = (const float*)d_in[0];
    const float* in_w  = (const float*)d_in[1];
    const float* in_b  = (const float*)d_in[2];
    const float* out_w = (const float*)d_in[3];
    const float* out_b = (const float*)d_in[4];
    const float* pos_w = (const float*)d_in[5];
    const float* pos_b = (const float*)d_in[6];
    float* out = (float*)d_out;

    k_prep<<<256, 256>>>(out_w, in_w);
    k_h   <<<NBI, 256>>>(x, in_b);
    k_m   <<<dim3(32, 8), 256>>>();
    k_main<<<NBI * 2, 256>>>(pos_w, pos_b, out_b, out);
}

// round 9
// speedup vs baseline: 1.1721x; 1.1654x over previous
#include <cuda_runtime.h>
#include <cstdint>

// Shapes for PairwiseEmbeddings: B=2, L=256, H=256, A=32, P=64
#define LL   256
#define NB   2
#define NBI  512          // B*L
#define AA   32
#define PP   64
#define HH   256
#define CP   2048         // A*P : cp = c*64 + p  (c-major, p fastest)

// Scratch (no cudaMalloc allowed): ~4.4 MB total
__device__ float g_h [NBI * AA];        // h[bi][a]                64 KB
__device__ float g_hT[NB * AA * LL];    // hT[b][c][j]             64 KB
__device__ float g_wT[HH * AA];         // in_w transposed [k][a]  32 KB
__device__ float g_W2[AA * CP];         // W2[a][c*64+p]          256 KB
__device__ float g_M [NBI * CP];        // M[bi][c*64+p]            4 MB

// ---------------------------------------------------------------------------
// Prep: transpose out_w -> W2[a][c*64+p], transpose in_w -> wT[k][a]
// ---------------------------------------------------------------------------
__global__ void k_prep(const float* __restrict__ out_w,
                       const float* __restrict__ in_w) {
    int idx = blockIdx.x * 256 + threadIdx.x;       // grid covers 65536
    if (idx < PP * AA * AA) {
        int p = idx >> 10;          // out_w flat = p*1024 + a*32 + c
        int a = (idx >> 5) & 31;
        int c = idx & 31;
        g_W2[a * CP + c * PP + p] = out_w[idx];
    }
    if (idx < AA * HH) {
        int a = idx >> 8;           // in_w flat = a*256 + k
        int k = idx & 255;
        g_wT[k * AA + a] = in_w[idx];
    }
}

// ---------------------------------------------------------------------------
// K1: h[bi][a] = sum_k x[bi][k] * in_w[a][k] + in_b[a]
// One block per bi row. Tail also writes the [b][c][j] transpose for k_main.
// ---------------------------------------------------------------------------
__global__ void k_h(const float* __restrict__ x,
                    const float* __restrict__ in_b) {
    __shared__ float red[256];
    int t  = threadIdx.x;
    int bi = blockIdx.x;
    int a  = t & 31;
    int kc = t >> 5;                 // 0..7
    const float* xr = x + bi * HH + kc * 32;     // uniform per warp
    const float* wr = g_wT + (kc * 32) * AA + a; // coalesced over lanes
    float acc = 0.f;
#pragma unroll
    for (int k = 0; k < 32; k++)
        acc += xr[k] * wr[k * AA];
    red[t] = acc;
    __syncthreads();
    if (t < 32) {
        float s = in_b[t];
#pragma unroll
        for (int q = 0; q < 8; q++) s += red[q * 32 + t];
        g_h[bi * AA + t] = s;
        int b = bi >> 8, i = bi & 255;
        g_hT[b * (AA * LL) + t * LL + i] = s;    // transposed copy
    }
}

// ---------------------------------------------------------------------------
// K2: M[bi][cp] = sum_a h[bi][a] * W2[a][cp]
// ---------------------------------------------------------------------------
__global__ void k_m() {
    __shared__ float hs[16 * AA];    // 2 KB
    int t   = threadIdx.x;
    int bi0 = blockIdx.x * 16;
    int cp  = blockIdx.y * 256 + t;

    for (int idx = t; idx < 16 * AA; idx += 256)
        hs[idx] = g_h[bi0 * AA + idx];
    __syncthreads();

    float acc[16];
#pragma unroll
    for (int i = 0; i < 16; i++) acc[i] = 0.f;

#pragma unroll
    for (int a = 0; a < AA; a++) {
        float w = g_W2[a * CP + cp];
#pragma unroll
        for (int i = 0; i < 16; i++)
            acc[i] = fmaf(hs[i * AA + a], w, acc[i]);
    }
#pragma unroll
    for (int i = 0; i < 16; i++)
        g_M[(bi0 + i) * CP + cp] = acc[i];
}

// ---------------------------------------------------------------------------
// K3 (dominant): out[bi][j][p] = sum_c M[bi][c][p] * h[b][j][c] + table[d][p]
// R9: balanced 8j x 8p tile (L1 phases == fma cycles per warp per c) at
// raised occupancy: 128-thread CTAs, launch_bounds(128,5) -> <=102 regs,
// 20 warps/SM (5/SMSP). Grid = 1024 CTAs (bi x j-half).
//   pg = t & 7   -> p  = pg*8 .. pg*8+7
//   jg = t >> 3  -> j  = j0 + jg*8 + jj, jj in 0..7   (jg 0..15)
// Per c per warp: 4 LDS.128 (16 phases) vs 32 FFMA2 (64 fma-cyc) — fma-favored
// with latency covered by 5 warps/SMSP.
// ---------------------------------------------------------------------------
__global__ void __launch_bounds__(128, 5)
k_main(const float* __restrict__ pos_w,
       const float* __restrict__ pos_b,
       const float* __restrict__ out_b,
       float* __restrict__ out) {
    __shared__ __align__(16) float ms [AA * PP];    // M[c][p]       8 KB
    __shared__ __align__(16) float hts[AA * 128];   // hT[c][jl]    16 KB
    __shared__ __align__(16) float ps [17 * 68];    // pos table   4.6 KB

    int t   = threadIdx.x;          // 0..127
    int bi  = blockIdx.x >> 1;
    int jh  = blockIdx.x & 1;
    int j0  = jh * 128;
    int b   = bi >> 8;
    int i   = bi & 255;

    // M slice for this (b,i): contiguous, coalesced (4 float4 per thread)
    {
        const float4* src = reinterpret_cast<const float4*>(&g_M[bi * CP]);
        float4* dst = reinterpret_cast<float4*>(ms);
#pragma unroll
        for (int k = 0; k < 4; k++)
            dst[k * 128 + t] = src[k * 128 + t];
    }

    // hT tile: c-major rows, j-slice [j0, j0+128) (8 float4 per thread)
    {
        const float4* src = reinterpret_cast<const float4*>(
            &g_hT[b * (AA * LL)]);
        float4* dst = reinterpret_cast<float4*>(hts);
        int jq0 = j0 >> 2;                       // float4 offset of j-slice
#pragma unroll
        for (int k = 0; k < 8; k++) {
            int idx4 = k * 128 + t;              // 0..1023
            int c   = idx4 >> 5;
            int jl4 = idx4 & 31;
            dst[c * 32 + jl4] = src[c * 64 + jq0 + jl4];
        }
    }

    // fold out_b + pos_b into pos table: ps[d][p]
#pragma unroll
    for (int k = 0; k < 9; k++) {
        int idx = k * 128 + t;
        if (idx < 17 * 64) {
            int d = idx >> 6, p = idx & 63;
            ps[d * 68 + p] = pos_w[p * 17 + d] + pos_b[p] + out_b[p];
        }
    }
    __syncthreads();

    int pg = t & 7;        // p-group (8 p)
    int jg = t >> 3;       // j-group (8 j), 0..15

    unsigned long long acc[32];    // [jj][k] : jj*4 + k, k over 4 p-pairs
#pragma unroll
    for (int k = 0; k < 32; k++) acc[k] = 0ULL;

    const ulonglong2* msv = reinterpret_cast<const ulonglong2*>(ms);
    const float4*     hv  = reinterpret_cast<const float4*>(hts);

#pragma unroll
    for (int c = 0; c < 32; c++) {
        // M[c][pg*8 .. pg*8+7]: float base c*64+pg*8 -> ull2 idx c*16+pg*2
        ulonglong2 ma = msv[c * 16 + pg * 2];
        ulonglong2 mb = msv[c * 16 + pg * 2 + 1];
        // h[c][jg*8 .. jg*8+7]: float base c*128+jg*8 -> float4 idx c*32+jg*2
        float4 h0 = hv[c * 32 + jg * 2];
        float4 h1 = hv[c * 32 + jg * 2 + 1];

        float hvals[8] = {h0.x, h0.y, h0.z, h0.w, h1.x, h1.y, h1.z, h1.w};
#pragma unroll
        for (int jj = 0; jj < 8; jj++) {
            unsigned int hu = __float_as_uint(hvals[jj]);
            unsigned long long h2;
            asm("mov.b64 %0, {%1, %1};" : "=l"(h2) : "r"(hu));
            asm("fma.rn.f32x2 %0, %1, %2, %0;" : "+l"(acc[jj*4+0]) : "l"(ma.x), "l"(h2));
            asm("fma.rn.f32x2 %0, %1, %2, %0;" : "+l"(acc[jj*4+1]) : "l"(ma.y), "l"(h2));
            asm("fma.rn.f32x2 %0, %1, %2, %0;" : "+l"(acc[jj*4+2]) : "l"(mb.x), "l"(h2));
            asm("fma.rn.f32x2 %0, %1, %2, %0;" : "+l"(acc[jj*4+3]) : "l"(mb.y), "l"(h2));
        }
    }

    // epilogue: packed add of rel-pos row, vectorized store
#pragma unroll
    for (int jj = 0; jj < 8; jj++) {
        int j = j0 + jg * 8 + jj;
        int d = i - j;
        d = (d < -8) ? -8 : ((d > 8) ? 8 : d);
        d += 8;
        const ulonglong2* pr =
            reinterpret_cast<const ulonglong2*>(&ps[d * 68 + pg * 8]);
        ulonglong2 p0 = pr[0], p1 = pr[1];
        ulonglong2 r0, r1;
        asm("add.rn.f32x2 %0, %1, %2;" : "=l"(r0.x) : "l"(acc[jj*4+0]), "l"(p0.x));
        asm("add.rn.f32x2 %0, %1, %2;" : "=l"(r0.y) : "l"(acc[jj*4+1]), "l"(p0.y));
        asm("add.rn.f32x2 %0, %1, %2;" : "=l"(r1.x) : "l"(acc[jj*4+2]), "l"(p1.x));
        asm("add.rn.f32x2 %0, %1, %2;" : "=l"(r1.y) : "l"(acc[jj*4+3]), "l"(p1.y));
        ulonglong2* ob = reinterpret_cast<ulonglong2*>(
            out + ((size_t)bi * LL + j) * PP + pg * 8);
        ob[0] = r0;
        ob[1] = r1;
    }
}

// ---------------------------------------------------------------------------
// Launch
// inputs (metadata order): inputs_embeds, in_w, in_b, out_w, out_b, pos_w, pos_b
// ---------------------------------------------------------------------------
extern "C" void kernel_launch(void* const* d_in, const int* in_sizes, int n_in,
                              void* d_out, int out_size) {
    const float* x     = (const float*)d_in[0];
    const float* in_w  = (const float*)d_in[1];
    const float* in_b  = (const float*)d_in[2];
    const float* out_w = (const float*)d_in[3];
    const float* out_b = (const float*)d_in[4];
    const float* pos_w = (const float*)d_in[5];
    const float* pos_b = (const float*)d_in[6];
    float* out = (float*)d_out;

    k_prep<<<256, 256>>>(out_w, in_w);
    k_h   <<<NBI, 256>>>(x, in_b);
    k_m   <<<dim3(32, 8), 256>>>();
    k_main<<<NBI * 2, 128>>>(pos_w, pos_b, out_b, out);
}